// round 8
// baseline (speedup 1.0000x reference)
#include <cuda_runtime.h>
#include <cuda_fp16.h>
#include <cstddef>

#define NN 50000
#define NE 800000
#define DIN 128
#define DHID 128
#define DOUT 64
#define NB   ((NN + 1023) / 1024)   // 49 scan blocks

// ---------------- scratch (__device__ globals; no allocation) ----------------
__device__ __half g_xw1[(size_t)NN * DHID];   // fp16 x@W1 (RAW)
__device__ float  g_agg1[(size_t)NN * DHID];
__device__ __half g_xw2[(size_t)NN * DOUT];   // fp16 (relu(agg1)@W2)*dis
__device__ float  g_dis[NN];
__device__ int    g_cnt[NN];    // zero-init; restored to 0 by k_scanF
__device__ int    g_cur[NN];
__device__ int    g_off[NN + 1];
__device__ int    g_esrc[NE];
__device__ int    g_bsum[NB];
__device__ int    g_flag[NB];   // zero-init; restored to 0 by k_fill

// ---------------- CSR build ----------------
__global__ void k_hist(const int* __restrict__ dst, int e4, int e) {
    int i = blockIdx.x * blockDim.x + threadIdx.x;
    if (i < e4) {
        int4 d = *(const int4*)(dst + i * 4);
        atomicAdd(&g_cnt[d.x], 1);
        atomicAdd(&g_cnt[d.y], 1);
        atomicAdd(&g_cnt[d.z], 1);
        atomicAdd(&g_cnt[d.w], 1);
    }
    int t = e4 * 4 + i;
    if (i < (e - e4 * 4)) atomicAdd(&g_cnt[dst[t]], 1);
}

// fused single-pass scan (decoupled lookback over <=49 blocks)
__global__ void k_scanF(int n, int nb) {
    __shared__ int warpsum[32];
    __shared__ int s_pre;
    const int tid = threadIdx.x, lane = tid & 31, wid = tid >> 5;
    const int bid = blockIdx.x;
    int i = bid * 1024 + tid;
    int v = (i < n) ? g_cnt[i] : 0;
    int x = v;
#pragma unroll
    for (int o = 1; o < 32; o <<= 1) {
        int t = __shfl_up_sync(0xFFFFFFFFu, x, o);
        if (lane >= o) x += t;
    }
    if (lane == 31) warpsum[wid] = x;
    __syncthreads();
    if (wid == 0) {
        int w = warpsum[lane];
#pragma unroll
        for (int o = 1; o < 32; o <<= 1) {
            int t = __shfl_up_sync(0xFFFFFFFFu, w, o);
            if (lane >= o) w += t;
        }
        warpsum[lane] = w;
    }
    __syncthreads();
    int warpbase = (wid == 0) ? 0 : warpsum[wid - 1];
    int local = warpbase + x - v;

    if (tid == 0) {
        g_bsum[bid] = warpsum[31];
        __threadfence();
        atomicExch(&g_flag[bid], 1);
    }
    if (wid == 0) {
        int p = 0;
        for (int idx = lane; idx < bid; idx += 32) {
            while (atomicAdd(&g_flag[idx], 0) == 0) {}
            p += atomicAdd(&g_bsum[idx], 0);
        }
#pragma unroll
        for (int o = 16; o > 0; o >>= 1)
            p += __shfl_down_sync(0xFFFFFFFFu, p, o);
        if (lane == 0) s_pre = p;
    }
    __syncthreads();
    int pre = s_pre;
    if (i < n) {
        int o = local + pre;
        g_off[i] = o;
        g_cur[i] = o;
        g_dis[i] = rsqrtf((float)v + 1.0f);
        g_cnt[i] = 0;
    }
    if (bid == nb - 1 && tid == 0) g_off[n] = pre + warpsum[31];
}

// fill: 4 edges per thread; resets scan flags
__global__ void k_fill(const int* __restrict__ src, const int* __restrict__ dst,
                       int e4, int e, int nb) {
    int i = blockIdx.x * blockDim.x + threadIdx.x;
    if (i < nb) g_flag[i] = 0;
    if (i < e4) {
        int4 d = *(const int4*)(dst + i * 4);
        int4 s = *(const int4*)(src + i * 4);
        int p0 = atomicAdd(&g_cur[d.x], 1);
        int p1 = atomicAdd(&g_cur[d.y], 1);
        int p2 = atomicAdd(&g_cur[d.z], 1);
        int p3 = atomicAdd(&g_cur[d.w], 1);
        g_esrc[p0] = s.x;
        g_esrc[p1] = s.y;
        g_esrc[p2] = s.z;
        g_esrc[p3] = s.w;
    }
    int t = e4 * 4 + i;
    if (i < (e - e4 * 4)) {
        int p = atomicAdd(&g_cur[dst[t]], 1);
        g_esrc[p] = src[t];
    }
}

// ---------------- packed f32x2 FMA helpers ----------------
__device__ __forceinline__ void fma2(unsigned long long& d,
                                     unsigned long long a,
                                     unsigned long long b) {
    asm("fma.rn.f32x2 %0, %1, %2, %0;" : "+l"(d) : "l"(a), "l"(b));
}
__device__ __forceinline__ unsigned long long bcast2(float a) {
    unsigned long long r;
    asm("mov.b64 %0, {%1, %1};" : "=l"(r) : "r"(__float_as_uint(a)));
    return r;
}

// ---------------- pipelined SGEMM (FFMA2, 2-stage smem ping-pong) -----------
// XWS(half) = (op(A) @ W) [* dis[row]]
template <int BN, int TN, bool RELU_IN, bool SCALE_DIS>
__global__ void __launch_bounds__(256, 2)
gemm_xws(const float* __restrict__ A, const float* __restrict__ W,
         __half* __restrict__ XWS, int M, int K, int N)
{
    constexpr int BM = 128, BK = 16, TM = 8;
    constexpr int BLD = (BK * BN / 4) / 256;   // B float4 loads per thread
    __shared__ float As[2][BK][BM];
    __shared__ float Bs[2][BK][BN];

    const int tid  = threadIdx.x;           // 256 threads
    const int row0 = blockIdx.x * BM;
    const int tx   = tid & 15;
    const int ty   = tid >> 4;

    // A-load geometry
    const int a_r0  = tid >> 2;              // 0..63   (l=0)
    const int a_r1  = a_r0 + 64;             //         (l=1)
    const int a_c4  = (tid & 3) * 4;
    // B-load geometry
    const int b_r   = tid / (BN / 4);
    const int b_c4  = (tid % (BN / 4)) * 4;

    unsigned long long acc2[TM][TN / 2];
#pragma unroll
    for (int i = 0; i < TM; i++)
#pragma unroll
        for (int j = 0; j < TN / 2; j++) acc2[i][j] = 0ULL;

    float4 a_st[2];
    float4 b_st[BLD];

    auto ldg_tiles = [&](int k0) {
#pragma unroll
        for (int l = 0; l < 2; l++) {
            int gr = row0 + (l ? a_r1 : a_r0);
            float4 av = make_float4(0.f, 0.f, 0.f, 0.f);
            if (gr < M) av = *(const float4*)(A + (size_t)gr * K + k0 + a_c4);
            if (RELU_IN) {
                av.x = fmaxf(av.x, 0.f); av.y = fmaxf(av.y, 0.f);
                av.z = fmaxf(av.z, 0.f); av.w = fmaxf(av.w, 0.f);
            }
            a_st[l] = av;
        }
#pragma unroll
        for (int l = 0; l < BLD; l++) {
            int r = b_r + l * (256 / (BN / 4));
            b_st[l] = *(const float4*)(W + (size_t)(k0 + r) * N + b_c4);
        }
    };
    auto sts_tiles = [&](int buf) {
#pragma unroll
        for (int l = 0; l < 2; l++) {
            int r = l ? a_r1 : a_r0;
            As[buf][a_c4 + 0][r] = a_st[l].x;
            As[buf][a_c4 + 1][r] = a_st[l].y;
            As[buf][a_c4 + 2][r] = a_st[l].z;
            As[buf][a_c4 + 3][r] = a_st[l].w;
        }
#pragma unroll
        for (int l = 0; l < BLD; l++) {
            int r = b_r + l * (256 / (BN / 4));
            *(float4*)&Bs[buf][r][b_c4] = b_st[l];
        }
    };

    // prologue
    ldg_tiles(0);
    sts_tiles(0);
    __syncthreads();

    const int NIT = K / BK;
    for (int it = 0; it < NIT; it++) {
        if (it + 1 < NIT) ldg_tiles((it + 1) * BK);   // prefetch next
        int cur = it & 1;
#pragma unroll
        for (int k = 0; k < BK; k++) {
            float a[TM];
            unsigned long long bp[TN / 2];
#pragma unroll
            for (int i = 0; i < TM; i += 4)
                *(float4*)&a[i] = *(const float4*)&As[cur][k][ty * TM + i];
#pragma unroll
            for (int j = 0; j < TN / 2; j++)
                bp[j] = *(const unsigned long long*)&Bs[cur][k][tx * TN + 2 * j];
#pragma unroll
            for (int i = 0; i < TM; i++) {
                unsigned long long ap = bcast2(a[i]);
#pragma unroll
                for (int j = 0; j < TN / 2; j++)
                    fma2(acc2[i][j], ap, bp[j]);
            }
        }
        if (it + 1 < NIT) {
            sts_tiles((it + 1) & 1);
            __syncthreads();
        }
    }

#pragma unroll
    for (int i = 0; i < TM; i++) {
        int gr = row0 + ty * TM + i;
        if (gr >= M) continue;
        float d = SCALE_DIS ? g_dis[gr] : 1.0f;
        __half2 h[TN / 2];
#pragma unroll
        for (int j = 0; j < TN / 2; j++) {
            float2 p = *(float2*)&acc2[i][j];
            h[j] = SCALE_DIS ? __floats2half2_rn(p.x * d, p.y * d)
                             : __floats2half2_rn(p.x, p.y);
        }
        __half* dstp = XWS + (size_t)gr * N + tx * TN;
        if (TN == 8) *(uint4*)dstp = *(uint4*)h;
        else         *(uint2*)dstp = *(uint2*)h;
    }
}

// ---------------- CSR aggregation, D=128 (half xw): one warp per node -------
__global__ void agg128h(const __half* __restrict__ xw,
                        const float* __restrict__ bias,
                        float* __restrict__ out, int n)
{
    int w = (blockIdx.x * blockDim.x + threadIdx.x) >> 5;
    int lane = threadIdx.x & 31;
    if (w >= n) return;
    int beg = g_off[w], end = g_off[w + 1];
    float dd = g_dis[w];

    uint2 us = *(const uint2*)(xw + (size_t)w * 128 + lane * 4);
    float2 s0 = __half22float2(*(__half2*)&us.x);
    float2 s1 = __half22float2(*(__half2*)&us.y);
    float4 acc = make_float4(s0.x * dd, s0.y * dd, s1.x * dd, s1.y * dd);

    int j = beg;
    for (; j + 4 <= end; j += 4) {
        int e0 = g_esrc[j], e1 = g_esrc[j + 1], e2 = g_esrc[j + 2], e3 = g_esrc[j + 3];
        float n0 = g_dis[e0], n1 = g_dis[e1], n2 = g_dis[e2], n3 = g_dis[e3];
        uint2 u0 = *(const uint2*)(xw + (size_t)e0 * 128 + lane * 4);
        uint2 u1 = *(const uint2*)(xw + (size_t)e1 * 128 + lane * 4);
        uint2 u2 = *(const uint2*)(xw + (size_t)e2 * 128 + lane * 4);
        uint2 u3 = *(const uint2*)(xw + (size_t)e3 * 128 + lane * 4);
        float2 a0 = __half22float2(*(__half2*)&u0.x), b0 = __half22float2(*(__half2*)&u0.y);
        float2 a1 = __half22float2(*(__half2*)&u1.x), b1 = __half22float2(*(__half2*)&u1.y);
        float2 a2 = __half22float2(*(__half2*)&u2.x), b2 = __half22float2(*(__half2*)&u2.y);
        float2 a3 = __half22float2(*(__half2*)&u3.x), b3 = __half22float2(*(__half2*)&u3.y);
        acc.x += a0.x * n0 + a1.x * n1 + a2.x * n2 + a3.x * n3;
        acc.y += a0.y * n0 + a1.y * n1 + a2.y * n2 + a3.y * n3;
        acc.z += b0.x * n0 + b1.x * n1 + b2.x * n2 + b3.x * n3;
        acc.w += b0.y * n0 + b1.y * n1 + b2.y * n2 + b3.y * n3;
    }
    for (; j < end; j++) {
        int s = g_esrc[j];
        float ns = g_dis[s];
        uint2 u = *(const uint2*)(xw + (size_t)s * 128 + lane * 4);
        float2 a = __half22float2(*(__half2*)&u.x);
        float2 b = __half22float2(*(__half2*)&u.y);
        acc.x += a.x * ns; acc.y += a.y * ns; acc.z += b.x * ns; acc.w += b.y * ns;
    }
    float4 bv = *(const float4*)(bias + lane * 4);
    acc.x = acc.x * dd + bv.x;
    acc.y = acc.y * dd + bv.y;
    acc.z = acc.z * dd + bv.z;
    acc.w = acc.w * dd + bv.w;
    *(float4*)(out + (size_t)w * 128 + lane * 4) = acc;
}

// ---------------- CSR aggregation, D=64 (half xws pre-scaled) ---------------
__global__ void agg64h(const __half* __restrict__ xws,
                       const float* __restrict__ bias,
                       float* __restrict__ out, int n)
{
    int w = (blockIdx.x * blockDim.x + threadIdx.x) >> 5;
    int lane = threadIdx.x & 31;
    if (w >= n) return;
    int beg = g_off[w], end = g_off[w + 1];
    float dd = g_dis[w];

    float2 acc = __half22float2(*(const __half2*)(xws + (size_t)w * 64 + lane * 2));

    int j = beg;
    for (; j + 4 <= end; j += 4) {
        int e0 = g_esrc[j], e1 = g_esrc[j + 1], e2 = g_esrc[j + 2], e3 = g_esrc[j + 3];
        float2 v0 = __half22float2(*(const __half2*)(xws + (size_t)e0 * 64 + lane * 2));
        float2 v1 = __half22float2(*(const __half2*)(xws + (size_t)e1 * 64 + lane * 2));
        float2 v2 = __half22float2(*(const __half2*)(xws + (size_t)e2 * 64 + lane * 2));
        float2 v3 = __half22float2(*(const __half2*)(xws + (size_t)e3 * 64 + lane * 2));
        acc.x += v0.x + v1.x + v2.x + v3.x;
        acc.y += v0.y + v1.y + v2.y + v3.y;
    }
    for (; j < end; j++) {
        int s = g_esrc[j];
        float2 v = __half22float2(*(const __half2*)(xws + (size_t)s * 64 + lane * 2));
        acc.x += v.x; acc.y += v.y;
    }
    float2 b = *(const float2*)(bias + lane * 2);
    acc.x = acc.x * dd + b.x;
    acc.y = acc.y * dd + b.y;
    *(float2*)(out + (size_t)w * 64 + lane * 2) = acc;
}

extern "C" void kernel_launch(void* const* d_in, const int* in_sizes, int n_in,
                              void* d_out, int out_size)
{
    const float* x  = (const float*)d_in[0];
    const int*   ei = (const int*)  d_in[1];
    const float* W1 = (const float*)d_in[2];
    const float* b1 = (const float*)d_in[3];
    const float* W2 = (const float*)d_in[4];
    const float* b2 = (const float*)d_in[5];
    float* out = (float*)d_out;

    const int N = in_sizes[0] / DIN;   // 50000
    const int E = in_sizes[1] / 2;     // 800000
    const int* src = ei;
    const int* dst = ei + E;

    __half *xw1, *xw2;
    float  *agg1;
    cudaGetSymbolAddress((void**)&xw1,  g_xw1);
    cudaGetSymbolAddress((void**)&agg1, g_agg1);
    cudaGetSymbolAddress((void**)&xw2,  g_xw2);

    static cudaStream_t s_side = nullptr;
    static cudaEvent_t  s_fork = nullptr, s_join = nullptr;
    if (s_side == nullptr) {
        cudaStreamCreateWithFlags(&s_side, cudaStreamNonBlocking);
        cudaEventCreateWithFlags(&s_fork, cudaEventDisableTiming);
        cudaEventCreateWithFlags(&s_join, cudaEventDisableTiming);
    }

    const int nb = (N + 1023) / 1024;
    const int e4 = E / 4;
    const int gemm_grid = (N + 127) / 128;

    // ---- fork: CSR build chain on side stream, GEMM1 on main stream ----
    cudaEventRecord(s_fork, 0);
    cudaStreamWaitEvent(s_side, s_fork, 0);

    k_hist <<<(e4 + 255) / 256, 256, 0, s_side>>>(dst, e4, E);
    k_scanF<<<nb, 1024, 0, s_side>>>(N, nb);
    k_fill <<<(e4 + 255) / 256, 256, 0, s_side>>>(src, dst, e4, E, nb);
    cudaEventRecord(s_join, s_side);

    // main: layer-1 GEMM (independent of graph structure), fp16 output
    gemm_xws<128, 8, false, false><<<gemm_grid, 256>>>(x, W1, xw1, N, DIN, DHID);

    cudaStreamWaitEvent(0, s_join, 0);

    // layer 1 aggregation (fp16 gathers, fp32 accumulate/output)
    agg128h<<<(N * 32 + 255) / 256, 256>>>(xw1, b1, agg1, N);

    // layer 2: fp16 output scaled by dis
    gemm_xws<64, 4, true, true><<<gemm_grid, 256>>>(agg1, W2, xw2, N, DHID, DOUT);
    agg64h<<<(N * 32 + 255) / 256, 256>>>(xw2, b2, out, N);
}

// round 9
// speedup vs baseline: 1.0557x; 1.0557x over previous
#include <cuda_runtime.h>
#include <cuda_fp16.h>
#include <cstddef>

#define NN 50000
#define NE 800000
#define DIN 128
#define DHID 128
#define DOUT 64
#define NB   ((NN + 1023) / 1024)   // 49 scan blocks

// ---------------- scratch (__device__ globals; no allocation) ----------------
__device__ __half g_xw1[(size_t)NN * DHID];   // fp16 x@W1 (RAW)
__device__ float  g_agg1[(size_t)NN * DHID];  // relu(gcn1) output
__device__ __half g_xw2[(size_t)NN * DOUT];   // fp16 (agg1@W2)*dis
__device__ float  g_dis[NN];
__device__ int    g_cnt[NN];    // zero-init; restored to 0 by k_scanF
__device__ int    g_cur[NN];
__device__ int    g_off[NN + 1];
__device__ int    g_esrc[NE];
__device__ int    g_bsum[NB];
__device__ int    g_flag[NB];   // zero-init; restored to 0 by k_fill

// ---------------- CSR build ----------------
__global__ void k_hist(const int* __restrict__ dst, int e4, int e) {
    int i = blockIdx.x * blockDim.x + threadIdx.x;
    if (i < e4) {
        int4 d = *(const int4*)(dst + i * 4);
        atomicAdd(&g_cnt[d.x], 1);
        atomicAdd(&g_cnt[d.y], 1);
        atomicAdd(&g_cnt[d.z], 1);
        atomicAdd(&g_cnt[d.w], 1);
    }
    int t = e4 * 4 + i;
    if (i < (e - e4 * 4)) atomicAdd(&g_cnt[dst[t]], 1);
}

// fused single-pass scan (decoupled lookback over <=49 blocks)
__global__ void k_scanF(int n, int nb) {
    __shared__ int warpsum[32];
    __shared__ int s_pre;
    const int tid = threadIdx.x, lane = tid & 31, wid = tid >> 5;
    const int bid = blockIdx.x;
    int i = bid * 1024 + tid;
    int v = (i < n) ? g_cnt[i] : 0;
    int x = v;
#pragma unroll
    for (int o = 1; o < 32; o <<= 1) {
        int t = __shfl_up_sync(0xFFFFFFFFu, x, o);
        if (lane >= o) x += t;
    }
    if (lane == 31) warpsum[wid] = x;
    __syncthreads();
    if (wid == 0) {
        int w = warpsum[lane];
#pragma unroll
        for (int o = 1; o < 32; o <<= 1) {
            int t = __shfl_up_sync(0xFFFFFFFFu, w, o);
            if (lane >= o) w += t;
        }
        warpsum[lane] = w;
    }
    __syncthreads();
    int warpbase = (wid == 0) ? 0 : warpsum[wid - 1];
    int local = warpbase + x - v;

    if (tid == 0) {
        g_bsum[bid] = warpsum[31];
        __threadfence();
        atomicExch(&g_flag[bid], 1);
    }
    if (wid == 0) {
        int p = 0;
        for (int idx = lane; idx < bid; idx += 32) {
            while (atomicAdd(&g_flag[idx], 0) == 0) {}
            p += atomicAdd(&g_bsum[idx], 0);
        }
#pragma unroll
        for (int o = 16; o > 0; o >>= 1)
            p += __shfl_down_sync(0xFFFFFFFFu, p, o);
        if (lane == 0) s_pre = p;
    }
    __syncthreads();
    int pre = s_pre;
    if (i < n) {
        int o = local + pre;
        g_off[i] = o;
        g_cur[i] = o;
        g_dis[i] = rsqrtf((float)v + 1.0f);
        g_cnt[i] = 0;
    }
    if (bid == nb - 1 && tid == 0) g_off[n] = pre + warpsum[31];
}

// fill: 4 edges per thread; resets scan flags
__global__ void k_fill(const int* __restrict__ src, const int* __restrict__ dst,
                       int e4, int e, int nb) {
    int i = blockIdx.x * blockDim.x + threadIdx.x;
    if (i < nb) g_flag[i] = 0;
    if (i < e4) {
        int4 d = *(const int4*)(dst + i * 4);
        int4 s = *(const int4*)(src + i * 4);
        int p0 = atomicAdd(&g_cur[d.x], 1);
        int p1 = atomicAdd(&g_cur[d.y], 1);
        int p2 = atomicAdd(&g_cur[d.z], 1);
        int p3 = atomicAdd(&g_cur[d.w], 1);
        g_esrc[p0] = s.x;
        g_esrc[p1] = s.y;
        g_esrc[p2] = s.z;
        g_esrc[p3] = s.w;
    }
    int t = e4 * 4 + i;
    if (i < (e - e4 * 4)) {
        int p = atomicAdd(&g_cur[dst[t]], 1);
        g_esrc[p] = src[t];
    }
}

// ---------------- packed f32x2 FMA helpers ----------------
__device__ __forceinline__ void fma2(unsigned long long& d,
                                     unsigned long long a,
                                     unsigned long long b) {
    asm("fma.rn.f32x2 %0, %1, %2, %0;" : "+l"(d) : "l"(a), "l"(b));
}
__device__ __forceinline__ unsigned long long bcast2(float a) {
    unsigned long long r;
    asm("mov.b64 %0, {%1, %1};" : "=l"(r) : "r"(__float_as_uint(a)));
    return r;
}

// ---------------- full-panel SGEMM (single sync, FFMA2) ---------------------
// K fixed = 128. BM=128 rows x BN=64 cols per CTA. Whole A panel (transposed,
// padded stride) + whole B panel resident in dynamic smem; one __syncthreads;
// 128 pure-compute k-steps. XWS(half) = (A @ W) [* dis[row]].
template <bool SCALE_DIS>
__global__ void __launch_bounds__(256, 2)
gemm_panel(const float* __restrict__ A, const float* __restrict__ W,
           __half* __restrict__ XWS, int M, int N)
{
    constexpr int KK = 128, BM = 128, BN = 64, SA = 132;  // SA: padded m-stride
    extern __shared__ float sm[];
    float* As = sm;                 // As[k*SA + m]  (transposed A panel)
    float* Bs = sm + KK * SA;       // Bs[k*BN + n]

    const int tid  = threadIdx.x;   // 256
    const int row0 = blockIdx.y * BM;
    const int col0 = blockIdx.x * BN;
    const int tx   = tid & 15;
    const int ty   = tid >> 4;

    // ---- load A panel: warp = 8 rows x 64B, scatter-transpose (<=2-way STS)
    {
        const int rb = tid >> 2;            // 0..63
        const int a4 = (tid & 3) * 4;       // 0,4,8,12
#pragma unroll
        for (int lr = 0; lr < 2; lr++) {
#pragma unroll
            for (int lc = 0; lc < 8; lc++) {
                int r  = rb + 64 * lr;
                int c4 = a4 + 16 * lc;
                int gr = row0 + r;
                float4 av = make_float4(0.f, 0.f, 0.f, 0.f);
                if (gr < M) av = *(const float4*)(A + (size_t)gr * KK + c4);
                As[(c4 + 0) * SA + r] = av.x;
                As[(c4 + 1) * SA + r] = av.y;
                As[(c4 + 2) * SA + r] = av.z;
                As[(c4 + 3) * SA + r] = av.w;
            }
        }
    }
    // ---- load B panel (row-major, conflict-free)
    {
        const int rb = tid >> 4;            // 0..15
        const int c4 = (tid & 15) * 4;      // 0..60
#pragma unroll
        for (int l = 0; l < 8; l++) {
            int r = rb + 16 * l;
            *(float4*)&Bs[r * BN + c4] =
                *(const float4*)(W + (size_t)r * N + col0 + c4);
        }
    }
    __syncthreads();

    unsigned long long acc2[8][2];
#pragma unroll
    for (int i = 0; i < 8; i++) { acc2[i][0] = 0ULL; acc2[i][1] = 0ULL; }

#pragma unroll 8
    for (int k = 0; k < KK; k++) {
        float a[8];
        *(float4*)&a[0] = *(const float4*)&As[k * SA + ty * 8];
        *(float4*)&a[4] = *(const float4*)&As[k * SA + ty * 8 + 4];
        unsigned long long bp[2];
        *(float4*)bp = *(const float4*)&Bs[k * BN + tx * 4];
#pragma unroll
        for (int i = 0; i < 8; i++) {
            unsigned long long ap = bcast2(a[i]);
            fma2(acc2[i][0], ap, bp[0]);
            fma2(acc2[i][1], ap, bp[1]);
        }
    }

#pragma unroll
    for (int i = 0; i < 8; i++) {
        int gr = row0 + ty * 8 + i;
        if (gr >= M) continue;
        float d = SCALE_DIS ? g_dis[gr] : 1.0f;
        float2 p0 = *(float2*)&acc2[i][0];
        float2 p1 = *(float2*)&acc2[i][1];
        __half2 h[2];
        h[0] = __floats2half2_rn(p0.x * d, p0.y * d);
        h[1] = __floats2half2_rn(p1.x * d, p1.y * d);
        *(uint2*)(XWS + (size_t)gr * N + col0 + tx * 4) = *(uint2*)h;
    }
}

// ---------------- CSR aggregation, D=128 (half xw): one warp per node -------
// agg1 = relu( dis*(self + sum xw[s]*dis[s]) + bias )   (relu fused here)
__global__ void agg128h(const __half* __restrict__ xw,
                        const float* __restrict__ bias,
                        float* __restrict__ out, int n)
{
    int w = (blockIdx.x * blockDim.x + threadIdx.x) >> 5;
    int lane = threadIdx.x & 31;
    if (w >= n) return;
    int beg = g_off[w], end = g_off[w + 1];
    float dd = g_dis[w];

    uint2 us = *(const uint2*)(xw + (size_t)w * 128 + lane * 4);
    float2 s0 = __half22float2(*(__half2*)&us.x);
    float2 s1 = __half22float2(*(__half2*)&us.y);
    float4 acc = make_float4(s0.x * dd, s0.y * dd, s1.x * dd, s1.y * dd);

    int j = beg;
    for (; j + 4 <= end; j += 4) {
        int e0 = g_esrc[j], e1 = g_esrc[j + 1], e2 = g_esrc[j + 2], e3 = g_esrc[j + 3];
        float n0 = g_dis[e0], n1 = g_dis[e1], n2 = g_dis[e2], n3 = g_dis[e3];
        uint2 u0 = *(const uint2*)(xw + (size_t)e0 * 128 + lane * 4);
        uint2 u1 = *(const uint2*)(xw + (size_t)e1 * 128 + lane * 4);
        uint2 u2 = *(const uint2*)(xw + (size_t)e2 * 128 + lane * 4);
        uint2 u3 = *(const uint2*)(xw + (size_t)e3 * 128 + lane * 4);
        float2 a0 = __half22float2(*(__half2*)&u0.x), b0 = __half22float2(*(__half2*)&u0.y);
        float2 a1 = __half22float2(*(__half2*)&u1.x), b1 = __half22float2(*(__half2*)&u1.y);
        float2 a2 = __half22float2(*(__half2*)&u2.x), b2 = __half22float2(*(__half2*)&u2.y);
        float2 a3 = __half22float2(*(__half2*)&u3.x), b3 = __half22float2(*(__half2*)&u3.y);
        acc.x += a0.x * n0 + a1.x * n1 + a2.x * n2 + a3.x * n3;
        acc.y += a0.y * n0 + a1.y * n1 + a2.y * n2 + a3.y * n3;
        acc.z += b0.x * n0 + b1.x * n1 + b2.x * n2 + b3.x * n3;
        acc.w += b0.y * n0 + b1.y * n1 + b2.y * n2 + b3.y * n3;
    }
    for (; j < end; j++) {
        int s = g_esrc[j];
        float ns = g_dis[s];
        uint2 u = *(const uint2*)(xw + (size_t)s * 128 + lane * 4);
        float2 a = __half22float2(*(__half2*)&u.x);
        float2 b = __half22float2(*(__half2*)&u.y);
        acc.x += a.x * ns; acc.y += a.y * ns; acc.z += b.x * ns; acc.w += b.y * ns;
    }
    float4 bv = *(const float4*)(bias + lane * 4);
    acc.x = fmaxf(acc.x * dd + bv.x, 0.0f);
    acc.y = fmaxf(acc.y * dd + bv.y, 0.0f);
    acc.z = fmaxf(acc.z * dd + bv.z, 0.0f);
    acc.w = fmaxf(acc.w * dd + bv.w, 0.0f);
    *(float4*)(out + (size_t)w * 128 + lane * 4) = acc;
}

// ---------------- CSR aggregation, D=64 (half xws pre-scaled) ---------------
__global__ void agg64h(const __half* __restrict__ xws,
                       const float* __restrict__ bias,
                       float* __restrict__ out, int n)
{
    int w = (blockIdx.x * blockDim.x + threadIdx.x) >> 5;
    int lane = threadIdx.x & 31;
    if (w >= n) return;
    int beg = g_off[w], end = g_off[w + 1];
    float dd = g_dis[w];

    float2 acc = __half22float2(*(const __half2*)(xws + (size_t)w * 64 + lane * 2));

    int j = beg;
    for (; j + 4 <= end; j += 4) {
        int e0 = g_esrc[j], e1 = g_esrc[j + 1], e2 = g_esrc[j + 2], e3 = g_esrc[j + 3];
        float2 v0 = __half22float2(*(const __half2*)(xws + (size_t)e0 * 64 + lane * 2));
        float2 v1 = __half22float2(*(const __half2*)(xws + (size_t)e1 * 64 + lane * 2));
        float2 v2 = __half22float2(*(const __half2*)(xws + (size_t)e2 * 64 + lane * 2));
        float2 v3 = __half22float2(*(const __half2*)(xws + (size_t)e3 * 64 + lane * 2));
        acc.x += v0.x + v1.x + v2.x + v3.x;
        acc.y += v0.y + v1.y + v2.y + v3.y;
    }
    for (; j < end; j++) {
        int s = g_esrc[j];
        float2 v = __half22float2(*(const __half2*)(xws + (size_t)s * 64 + lane * 2));
        acc.x += v.x; acc.y += v.y;
    }
    float2 b = *(const float2*)(bias + lane * 2);
    acc.x = acc.x * dd + b.x;
    acc.y = acc.y * dd + b.y;
    *(float2*)(out + (size_t)w * 64 + lane * 2) = acc;
}

extern "C" void kernel_launch(void* const* d_in, const int* in_sizes, int n_in,
                              void* d_out, int out_size)
{
    const float* x  = (const float*)d_in[0];
    const int*   ei = (const int*)  d_in[1];
    const float* W1 = (const float*)d_in[2];
    const float* b1 = (const float*)d_in[3];
    const float* W2 = (const float*)d_in[4];
    const float* b2 = (const float*)d_in[5];
    float* out = (float*)d_out;

    const int N = in_sizes[0] / DIN;   // 50000
    const int E = in_sizes[1] / 2;     // 800000
    const int* src = ei;
    const int* dst = ei + E;

    __half *xw1, *xw2;
    float  *agg1;
    cudaGetSymbolAddress((void**)&xw1,  g_xw1);
    cudaGetSymbolAddress((void**)&agg1, g_agg1);
    cudaGetSymbolAddress((void**)&xw2,  g_xw2);

    constexpr int GEMM_SMEM = (128 * 132 + 128 * 64) * 4;   // 100352 B

    static cudaStream_t s_side = nullptr;
    static cudaEvent_t  s_fork = nullptr, s_join = nullptr;
    if (s_side == nullptr) {
        cudaStreamCreateWithFlags(&s_side, cudaStreamNonBlocking);
        cudaEventCreateWithFlags(&s_fork, cudaEventDisableTiming);
        cudaEventCreateWithFlags(&s_join, cudaEventDisableTiming);
        cudaFuncSetAttribute(gemm_panel<false>,
                             cudaFuncAttributeMaxDynamicSharedMemorySize, GEMM_SMEM);
        cudaFuncSetAttribute(gemm_panel<true>,
                             cudaFuncAttributeMaxDynamicSharedMemorySize, GEMM_SMEM);
    }

    const int nb = (N + 1023) / 1024;
    const int e4 = E / 4;
    const int gemm_grid = (N + 127) / 128;

    // ---- fork: CSR build chain on side stream, GEMM1 on main stream ----
    cudaEventRecord(s_fork, 0);
    cudaStreamWaitEvent(s_side, s_fork, 0);

    k_hist <<<(e4 + 255) / 256, 256, 0, s_side>>>(dst, e4, E);
    k_scanF<<<nb, 1024, 0, s_side>>>(N, nb);
    k_fill <<<(e4 + 255) / 256, 256, 0, s_side>>>(src, dst, e4, E, nb);
    cudaEventRecord(s_join, s_side);

    // main: layer-1 GEMM (independent of graph structure), fp16 raw output
    gemm_panel<false><<<dim3(2, gemm_grid), 256, GEMM_SMEM>>>(x, W1, xw1, N, DHID);

    cudaStreamWaitEvent(0, s_join, 0);

    // layer 1 aggregation (+relu fused into output)
    agg128h<<<(N * 32 + 255) / 256, 256>>>(xw1, b1, agg1, N);

    // layer 2 GEMM (agg1 already relu'd), dis-scaled fp16 output
    gemm_panel<true><<<dim3(1, gemm_grid), 256, GEMM_SMEM>>>(agg1, W2, xw2, N, DOUT);
    agg64h<<<(N * 32 + 255) / 256, 256>>>(xw2, b2, out, N);
}